// round 4
// baseline (speedup 1.0000x reference)
#include <cuda_runtime.h>
#include <cstdint>
#include <math.h>

#define N_NODES 50000
#define N_EDGES 800000
#define D0 1024
#define D1 512
#define D2 128
#define DOUT 14

// ---------------- scratch (device globals; no allocs allowed) ----------------
__device__ float g_deg[N_NODES];
__device__ float g_dis[N_NODES];
__device__ int   g_cnt[N_NODES];
__device__ int   g_rowptr[N_NODES + 1];
__device__ int   g_src[N_EDGES];
__device__ float g_wgt[N_EDGES];
__device__ float g_h1[(size_t)N_NODES * D1];   // X @ W1
__device__ float g_a1[(size_t)N_NODES * D1];   // relu(norm-agg + b1)
__device__ float g_h2[(size_t)N_NODES * D2];   // a1 @ W2
__device__ int   g_is64;

// ---------------- edge-index dtype detection (int64 vs int32) ----------------
__global__ void detect_idx_kernel(const void* eidx) {
    if (threadIdx.x == 0 && blockIdx.x == 0) {
        const int* p = (const int*)eidx;
        int ok64 = 1;
        for (int i = 1; i < 2048; i += 2) {
            if (p[i] != 0) { ok64 = 0; break; }
        }
        g_is64 = ok64;
    }
}

__device__ __forceinline__ int get_idx(const void* base, long i) {
    if (g_is64) return (int)((const long long*)base)[i];
    return ((const int*)base)[i];
}

// ---------------- degree / normalization / CSR build ----------------
__global__ void init_kernel() {
    int i = blockIdx.x * blockDim.x + threadIdx.x;
    if (i < N_NODES) { g_deg[i] = 1.0f; g_cnt[i] = 0; }
}

__global__ void edge_deg_kernel(const void* eidx, const float* __restrict__ ew) {
    int e = blockIdx.x * blockDim.x + threadIdx.x;
    if (e < N_EDGES) {
        int c = get_idx(eidx, (long)N_EDGES + e);
        atomicAdd(&g_deg[c], ew[e]);
        atomicAdd(&g_cnt[c], 1);
    }
}

__global__ void dis_kernel() {
    int i = blockIdx.x * blockDim.x + threadIdx.x;
    if (i < N_NODES) g_dis[i] = rsqrtf(g_deg[i]);
}

__global__ void scan_kernel() {
    __shared__ int part[1024];
    int tid = threadIdx.x;
    const int chunk = (N_NODES + 1023) / 1024;
    int start = tid * chunk;
    int end = start + chunk; if (end > N_NODES) end = N_NODES;
    int s = 0;
    for (int i = start; i < end; i++) s += g_cnt[i];
    part[tid] = s;
    __syncthreads();
    if (tid == 0) {
        int run = 0;
        for (int i = 0; i < 1024; i++) { int v = part[i]; part[i] = run; run += v; }
        g_rowptr[N_NODES] = run;
    }
    __syncthreads();
    int run = part[tid];
    for (int i = start; i < end; i++) {
        g_rowptr[i] = run;
        run += g_cnt[i];
        g_cnt[i] = 0;
    }
}

__global__ void scatter_kernel(const void* eidx, const float* __restrict__ ew) {
    int e = blockIdx.x * blockDim.x + threadIdx.x;
    if (e < N_EDGES) {
        int r = get_idx(eidx, e);
        int c = get_idx(eidx, (long)N_EDGES + e);
        int pos = g_rowptr[c] + atomicAdd(&g_cnt[c], 1);
        g_src[pos] = r;
        g_wgt[pos] = ew[e] * g_dis[r];
    }
}

// ---------------- tf32 tensor-core GEMM, cp.async double-buffered ----------------
// BM=128, BN=128, BK=32; 256 threads = 8 warps (4x2); warp tile 32x64.
// Raw fp32 fed to mma.tf32 (HW truncates mantissa) — no cvt anywhere.
#define BM 128
#define BN 128
#define BK 32
#define AS_STRIDE 36            // BK+4: frag banks (4g+t)%32 bijective
#define BS_STRIDE 136           // BN+8: frag banks (8t+g)%32 bijective
#define AS_SZ (BM * AS_STRIDE)  // 4608 floats
#define BS_SZ (BK * BS_STRIDE)  // 4352 floats
#define GEMM_SMEM_BYTES (2 * (AS_SZ + BS_SZ) * 4)  // 71680

__device__ __forceinline__ void mma_tf32(float* d, const float* a, const float* b) {
    asm volatile(
        "mma.sync.aligned.m16n8k8.row.col.f32.tf32.tf32.f32 "
        "{%0,%1,%2,%3}, {%4,%5,%6,%7}, {%8,%9}, {%0,%1,%2,%3};"
        : "+f"(d[0]), "+f"(d[1]), "+f"(d[2]), "+f"(d[3])
        : "f"(a[0]), "f"(a[1]), "f"(a[2]), "f"(a[3]),
          "f"(b[0]), "f"(b[1]));
}

__device__ __forceinline__ void cp_async16(void* smem_ptr, const void* gptr, int srcsize) {
    unsigned int sa = (unsigned int)__cvta_generic_to_shared(smem_ptr);
    asm volatile("cp.async.cg.shared.global [%0], [%1], 16, %2;\n"
                 :: "r"(sa), "l"(gptr), "r"(srcsize));
}

__device__ __forceinline__ void load_tiles(
    const float* __restrict__ A, const float* __restrict__ B,
    int M, int K, int N, int rowBase, int colBase, int k0,
    float* As, float* Bs, int tid)
{
    int lm  = tid >> 3;          // 0..31
    int lk4 = (tid & 7) * 4;     // 0..28
    int bk  = tid >> 5;          // 0..7
    int bn4 = (tid & 31) * 4;    // 0..124
#pragma unroll
    for (int p = 0; p < 4; p++) {
        int m = p * 32 + lm;
        int gr = rowBase + m;
        int sz = (gr < M) ? 16 : 0;
        int grc = gr < M ? gr : (M - 1);
        cp_async16(&As[m * AS_STRIDE + lk4], A + (size_t)grc * K + k0 + lk4, sz);
    }
#pragma unroll
    for (int p = 0; p < 4; p++) {
        int kk = p * 8 + bk;
        cp_async16(&Bs[kk * BS_STRIDE + bn4], B + (size_t)(k0 + kk) * N + colBase + bn4, 16);
    }
}

__global__ __launch_bounds__(256, 2)
void tf32gemm(const float* __restrict__ A, const float* __restrict__ B,
              float* __restrict__ C, int M, int K, int N) {
    extern __shared__ float smem_dyn[];
    float* AsBase = smem_dyn;                 // [2][AS_SZ]
    float* BsBase = smem_dyn + 2 * AS_SZ;     // [2][BS_SZ]

    int tid = threadIdx.x;
    int warp = tid >> 5, lane = tid & 31;
    int g = lane >> 2, t = lane & 3;
    int wm = (warp >> 1) * 32;
    int wn = (warp & 1) * 64;

    int rowBase = blockIdx.y * BM;
    int colBase = blockIdx.x * BN;

    float acc[2][8][4];
#pragma unroll
    for (int mi = 0; mi < 2; mi++)
#pragma unroll
        for (int ni = 0; ni < 8; ni++)
#pragma unroll
            for (int r = 0; r < 4; r++) acc[mi][ni][r] = 0.f;

    // prologue
    load_tiles(A, B, M, K, N, rowBase, colBase, 0, AsBase, BsBase, tid);
    asm volatile("cp.async.commit_group;\n");

    int buf = 0;
    for (int k0 = 0; k0 < K; k0 += BK) {
        bool has_next = (k0 + BK) < K;
        if (has_next) {
            load_tiles(A, B, M, K, N, rowBase, colBase, k0 + BK,
                       AsBase + (buf ^ 1) * AS_SZ, BsBase + (buf ^ 1) * BS_SZ, tid);
            asm volatile("cp.async.commit_group;\n");
            asm volatile("cp.async.wait_group 1;\n");
        } else {
            asm volatile("cp.async.wait_group 0;\n");
        }
        __syncthreads();

        const float* As = AsBase + buf * AS_SZ;
        const float* Bs = BsBase + buf * BS_SZ;
#pragma unroll
        for (int kk = 0; kk < BK; kk += 8) {
            float a[2][4];
#pragma unroll
            for (int mi = 0; mi < 2; mi++) {
                int row = wm + mi * 16;
                a[mi][0] = As[(row + g    ) * AS_STRIDE + kk + t    ];
                a[mi][1] = As[(row + g + 8) * AS_STRIDE + kk + t    ];
                a[mi][2] = As[(row + g    ) * AS_STRIDE + kk + t + 4];
                a[mi][3] = As[(row + g + 8) * AS_STRIDE + kk + t + 4];
            }
            float b[8][2];
#pragma unroll
            for (int ni = 0; ni < 8; ni++) {
                int col = wn + ni * 8;
                b[ni][0] = Bs[(kk + t    ) * BS_STRIDE + col + g];
                b[ni][1] = Bs[(kk + t + 4) * BS_STRIDE + col + g];
            }
#pragma unroll
            for (int mi = 0; mi < 2; mi++)
#pragma unroll
                for (int ni = 0; ni < 8; ni++)
                    mma_tf32(acc[mi][ni], a[mi], b[ni]);
        }
        __syncthreads();
        buf ^= 1;
    }

    // epilogue
#pragma unroll
    for (int mi = 0; mi < 2; mi++) {
        int row0 = rowBase + wm + mi * 16 + g;
        int row1 = row0 + 8;
#pragma unroll
        for (int ni = 0; ni < 8; ni++) {
            int col = colBase + wn + ni * 8 + t * 2;
            if (row0 < M)
                *(float2*)(C + (size_t)row0 * N + col) =
                    make_float2(acc[mi][ni][0], acc[mi][ni][1]);
            if (row1 < M)
                *(float2*)(C + (size_t)row1 * N + col) =
                    make_float2(acc[mi][ni][2], acc[mi][ni][3]);
        }
    }
}

// ---------------- aggregation layer 1: 512 features, 1 warp / node ----------------
__global__ __launch_bounds__(256)
void agg1_kernel(const float* __restrict__ b1) {
    int node = blockIdx.x * 8 + (threadIdx.x >> 5);
    if (node >= N_NODES) return;
    int lane = threadIdx.x & 31;
    const float4* h = (const float4*)g_h1;
    float dc = g_dis[node];

    float4 acc[4];
#pragma unroll
    for (int i = 0; i < 4; i++) {
        float4 v = h[(size_t)node * 128 + lane + i * 32];
        acc[i] = make_float4(v.x * dc, v.y * dc, v.z * dc, v.w * dc);
    }
    int beg = g_rowptr[node], end = g_rowptr[node + 1];
    for (int e = beg; e < end; e++) {
        int r = g_src[e];
        float w = g_wgt[e];
        const float4* hr = h + (size_t)r * 128;
#pragma unroll
        for (int i = 0; i < 4; i++) {
            float4 v = hr[lane + i * 32];
            acc[i].x += w * v.x; acc[i].y += w * v.y;
            acc[i].z += w * v.z; acc[i].w += w * v.w;
        }
    }
    float4* out = (float4*)g_a1;
    const float4* bb4 = (const float4*)b1;
#pragma unroll
    for (int i = 0; i < 4; i++) {
        float4 bb = bb4[lane + i * 32];
        float4 o;
        o.x = fmaxf(dc * acc[i].x + bb.x, 0.f);
        o.y = fmaxf(dc * acc[i].y + bb.y, 0.f);
        o.z = fmaxf(dc * acc[i].z + bb.z, 0.f);
        o.w = fmaxf(dc * acc[i].w + bb.w, 0.f);
        out[(size_t)node * 128 + lane + i * 32] = o;
    }
}

// ---------------- aggregation layer 2 fused with FC(128->14)+sigmoid ----------------
__global__ __launch_bounds__(256)
void agg2_fc_kernel(const float* __restrict__ b2, const float* __restrict__ Wfc,
                    const float* __restrict__ bfc, float* __restrict__ out) {
    __shared__ float sh[8][128];
    __shared__ float sWfc[D2 * DOUT];
    for (int i = threadIdx.x; i < D2 * DOUT; i += blockDim.x) sWfc[i] = Wfc[i];
    __syncthreads();

    int wid = threadIdx.x >> 5;
    int lane = threadIdx.x & 31;
    int node = blockIdx.x * 8 + wid;

    if (node < N_NODES) {
        const float4* h = (const float4*)g_h2;
        float dc = g_dis[node];
        float4 v = h[(size_t)node * 32 + lane];
        float4 acc = make_float4(v.x * dc, v.y * dc, v.z * dc, v.w * dc);
        int beg = g_rowptr[node], end = g_rowptr[node + 1];
        for (int e = beg; e < end; e++) {
            int r = g_src[e];
            float w = g_wgt[e];
            float4 u = h[(size_t)r * 32 + lane];
            acc.x += w * u.x; acc.y += w * u.y; acc.z += w * u.z; acc.w += w * u.w;
        }
        float4 bb = ((const float4*)b2)[lane];
        sh[wid][lane * 4 + 0] = fmaxf(dc * acc.x + bb.x, 0.f);
        sh[wid][lane * 4 + 1] = fmaxf(dc * acc.y + bb.y, 0.f);
        sh[wid][lane * 4 + 2] = fmaxf(dc * acc.z + bb.z, 0.f);
        sh[wid][lane * 4 + 3] = fmaxf(dc * acc.w + bb.w, 0.f);
    }
    __syncwarp();
    if (node < N_NODES && lane < DOUT) {
        float s = bfc[lane];
#pragma unroll 8
        for (int d = 0; d < D2; d++) s += sh[wid][d] * sWfc[d * DOUT + lane];
        out[(size_t)node * DOUT + lane] = 1.f / (1.f + expf(-s));
    }
}

// ---------------- launch ----------------
extern "C" void kernel_launch(void* const* d_in, const int* in_sizes, int n_in,
                              void* d_out, int out_size) {
    const float* x   = (const float*)d_in[0];
    const void*  eix = d_in[1];
    const float* ew  = (const float*)d_in[2];
    const float* W1  = (const float*)d_in[3];
    const float* b1  = (const float*)d_in[4];
    const float* W2  = (const float*)d_in[5];
    const float* b2  = (const float*)d_in[6];
    const float* Wfc = (const float*)d_in[7];
    const float* bfc = (const float*)d_in[8];
    float* out = (float*)d_out;

    float *h1p, *a1p, *h2p;
    cudaGetSymbolAddress((void**)&h1p, g_h1);
    cudaGetSymbolAddress((void**)&a1p, g_a1);
    cudaGetSymbolAddress((void**)&h2p, g_h2);

    static int smem_set = 0;
    if (!smem_set) {
        cudaFuncSetAttribute(tf32gemm, cudaFuncAttributeMaxDynamicSharedMemorySize,
                             GEMM_SMEM_BYTES);
        smem_set = 1;
    }

    const int TB = 256;
    detect_idx_kernel<<<1, 32>>>(eix);
    init_kernel<<<(N_NODES + TB - 1) / TB, TB>>>();
    edge_deg_kernel<<<(N_EDGES + TB - 1) / TB, TB>>>(eix, ew);
    dis_kernel<<<(N_NODES + TB - 1) / TB, TB>>>();
    scan_kernel<<<1, 1024>>>();
    scatter_kernel<<<(N_EDGES + TB - 1) / TB, TB>>>(eix, ew);

    dim3 g1(D1 / BN, (N_NODES + BM - 1) / BM);
    tf32gemm<<<g1, 256, GEMM_SMEM_BYTES>>>(x, W1, h1p, N_NODES, D0, D1);

    agg1_kernel<<<(N_NODES + 7) / 8, 256>>>(b1);

    dim3 g2(D2 / BN, (N_NODES + BM - 1) / BM);
    tf32gemm<<<g2, 256, GEMM_SMEM_BYTES>>>(a1p, W2, h2p, N_NODES, D1, D2);

    agg2_fc_kernel<<<(N_NODES + 7) / 8, 256>>>(b2, Wfc, bfc, out);
}

// round 5
// speedup vs baseline: 1.3709x; 1.3709x over previous
#include <cuda_runtime.h>
#include <cstdint>
#include <math.h>

#define N_NODES 50000
#define N_EDGES 800000
#define D0 1024
#define D1 512
#define D2 128
#define DOUT 14

// ---------------- scratch (device globals; no allocs allowed) ----------------
__device__ float g_deg[N_NODES];
__device__ float g_dis[N_NODES];
__device__ int   g_cnt[N_NODES];
__device__ int   g_rowptr[N_NODES + 1];
__device__ int   g_src[N_EDGES];
__device__ float g_wgt[N_EDGES];
__device__ float g_h1[(size_t)N_NODES * D1];   // X @ W1
__device__ float g_a1[(size_t)N_NODES * D1];   // relu(norm-agg + b1)
__device__ float g_h2[(size_t)N_NODES * D2];   // a1 @ W2
__device__ int   g_is64;

// ---------------- edge-index dtype detection (int64 vs int32) ----------------
__global__ void detect_idx_kernel(const void* eidx) {
    if (threadIdx.x == 0 && blockIdx.x == 0) {
        const int* p = (const int*)eidx;
        int ok64 = 1;
        for (int i = 1; i < 2048; i += 2) {
            if (p[i] != 0) { ok64 = 0; break; }
        }
        g_is64 = ok64;
    }
}

__device__ __forceinline__ int get_idx(const void* base, long i) {
    if (g_is64) return (int)((const long long*)base)[i];
    return ((const int*)base)[i];
}

// ---------------- degree / normalization / CSR build ----------------
__global__ void init_kernel() {
    int i = blockIdx.x * blockDim.x + threadIdx.x;
    if (i < N_NODES) { g_deg[i] = 1.0f; g_cnt[i] = 0; }
}

__global__ void edge_deg_kernel(const void* eidx, const float* __restrict__ ew) {
    int e = blockIdx.x * blockDim.x + threadIdx.x;
    if (e < N_EDGES) {
        int c = get_idx(eidx, (long)N_EDGES + e);
        atomicAdd(&g_deg[c], ew[e]);
        atomicAdd(&g_cnt[c], 1);
    }
}

__global__ void dis_kernel() {
    int i = blockIdx.x * blockDim.x + threadIdx.x;
    if (i < N_NODES) g_dis[i] = rsqrtf(g_deg[i]);
}

__global__ void scan_kernel() {
    __shared__ int part[1024];
    int tid = threadIdx.x;
    const int chunk = (N_NODES + 1023) / 1024;
    int start = tid * chunk;
    int end = start + chunk; if (end > N_NODES) end = N_NODES;
    int s = 0;
    for (int i = start; i < end; i++) s += g_cnt[i];
    part[tid] = s;
    __syncthreads();
    if (tid == 0) {
        int run = 0;
        for (int i = 0; i < 1024; i++) { int v = part[i]; part[i] = run; run += v; }
        g_rowptr[N_NODES] = run;
    }
    __syncthreads();
    int run = part[tid];
    for (int i = start; i < end; i++) {
        g_rowptr[i] = run;
        run += g_cnt[i];
        g_cnt[i] = 0;
    }
}

__global__ void scatter_kernel(const void* eidx, const float* __restrict__ ew) {
    int e = blockIdx.x * blockDim.x + threadIdx.x;
    if (e < N_EDGES) {
        int r = get_idx(eidx, e);
        int c = get_idx(eidx, (long)N_EDGES + e);
        int pos = g_rowptr[c] + atomicAdd(&g_cnt[c], 1);
        g_src[pos] = r;
        g_wgt[pos] = ew[e] * g_dis[r];
    }
}

// ---------------- tf32 tensor-core GEMM, cp.async 3-stage, BK=16 ----------------
// BM=128, BN=128, BK=16; 256 threads = 8 warps (4x2); warp tile 32x64.
// Raw fp32 fed to mma.tf32 (HW truncates mantissa) — no cvt anywhere.
#define BM 128
#define BN 128
#define BK 16
#define AS_STRIDE 20            // BK+4: frag lane banks (20g+t)%32 bijective
#define BS_STRIDE 136           // BN+8: frag lane banks (8t+g)%32 bijective
#define AS_SZ (BM * AS_STRIDE)  // 2560 floats
#define BS_SZ (BK * BS_STRIDE)  // 2176 floats
#define STAGE_SZ (AS_SZ + BS_SZ)            // 4736 floats
#define GEMM_SMEM_BYTES (3 * STAGE_SZ * 4)  // 56832 B

__device__ __forceinline__ void mma_tf32(float* d, const float* a, const float* b) {
    asm volatile(
        "mma.sync.aligned.m16n8k8.row.col.f32.tf32.tf32.f32 "
        "{%0,%1,%2,%3}, {%4,%5,%6,%7}, {%8,%9}, {%0,%1,%2,%3};"
        : "+f"(d[0]), "+f"(d[1]), "+f"(d[2]), "+f"(d[3])
        : "f"(a[0]), "f"(a[1]), "f"(a[2]), "f"(a[3]),
          "f"(b[0]), "f"(b[1]));
}

__device__ __forceinline__ void cp_async16(float* smem_ptr, const float* gptr, int srcsize) {
    unsigned int sa = (unsigned int)__cvta_generic_to_shared(smem_ptr);
    asm volatile("cp.async.cg.shared.global [%0], [%1], 16, %2;\n"
                 :: "r"(sa), "l"(gptr), "r"(srcsize));
}

// Load one BK=16 stage: per thread 2 A + 2 B cp.asyncs.
__device__ __forceinline__ void load_stage(
    const float* __restrict__ A, const float* __restrict__ B,
    int M, int K, int N, int rowBase, int colBase, int k0,
    float* As, float* Bs, int tid)
{
    int ar  = tid >> 2;          // 0..63
    int ac4 = (tid & 3) * 4;     // 0,4,8,12
    int bk  = tid >> 5;          // 0..7
    int bn4 = (tid & 31) * 4;    // 0..124
#pragma unroll
    for (int p = 0; p < 2; p++) {
        int m = p * 64 + ar;
        int gr = rowBase + m;
        int sz = (gr < M) ? 16 : 0;
        int grc = (gr < M) ? gr : 0;
        cp_async16(&As[m * AS_STRIDE + ac4], A + (size_t)grc * K + k0 + ac4, sz);
    }
#pragma unroll
    for (int p = 0; p < 2; p++) {
        int kk = p * 8 + bk;
        cp_async16(&Bs[kk * BS_STRIDE + bn4], B + (size_t)(k0 + kk) * N + colBase + bn4, 16);
    }
}

__global__ __launch_bounds__(256, 2)
void tf32gemm(const float* __restrict__ A, const float* __restrict__ B,
              float* __restrict__ C, int M, int K, int N) {
    extern __shared__ float smem_dyn[];

    int tid = threadIdx.x;
    int warp = tid >> 5, lane = tid & 31;
    int g = lane >> 2, t = lane & 3;
    int wm = (warp >> 1) * 32;
    int wn = (warp & 1) * 64;

    int rowBase = blockIdx.y * BM;
    int colBase = blockIdx.x * BN;

    float acc[2][8][4];
#pragma unroll
    for (int mi = 0; mi < 2; mi++)
#pragma unroll
        for (int ni = 0; ni < 8; ni++)
#pragma unroll
            for (int r = 0; r < 4; r++) acc[mi][ni][r] = 0.f;

    float* a_cur = smem_dyn;
    float* a_nxt = smem_dyn + STAGE_SZ;
    float* a_spr = smem_dyn + 2 * STAGE_SZ;
    float* b_cur = a_cur + AS_SZ;
    float* b_nxt = a_nxt + AS_SZ;
    float* b_spr = a_spr + AS_SZ;

    int niter = K / BK;

    // prologue: stages 0 and 1
    load_stage(A, B, M, K, N, rowBase, colBase, 0, a_cur, b_cur, tid);
    asm volatile("cp.async.commit_group;\n");
    if (niter > 1) {
        load_stage(A, B, M, K, N, rowBase, colBase, BK, a_nxt, b_nxt, tid);
        asm volatile("cp.async.commit_group;\n");
    }

    for (int i = 0; i < niter; i++) {
        if (i + 2 < niter) {
            load_stage(A, B, M, K, N, rowBase, colBase, (i + 2) * BK, a_spr, b_spr, tid);
            asm volatile("cp.async.commit_group;\n");
            asm volatile("cp.async.wait_group 2;\n");
        } else if (i + 1 < niter) {
            asm volatile("cp.async.wait_group 1;\n");
        } else {
            asm volatile("cp.async.wait_group 0;\n");
        }
        __syncthreads();

#pragma unroll
        for (int kk = 0; kk < BK; kk += 8) {
            float a[2][4];
#pragma unroll
            for (int mi = 0; mi < 2; mi++) {
                int row = wm + mi * 16;
                a[mi][0] = a_cur[(row + g    ) * AS_STRIDE + kk + t    ];
                a[mi][1] = a_cur[(row + g + 8) * AS_STRIDE + kk + t    ];
                a[mi][2] = a_cur[(row + g    ) * AS_STRIDE + kk + t + 4];
                a[mi][3] = a_cur[(row + g + 8) * AS_STRIDE + kk + t + 4];
            }
            float b[8][2];
#pragma unroll
            for (int ni = 0; ni < 8; ni++) {
                int col = wn + ni * 8;
                b[ni][0] = b_cur[(kk + t    ) * BS_STRIDE + col + g];
                b[ni][1] = b_cur[(kk + t + 4) * BS_STRIDE + col + g];
            }
#pragma unroll
            for (int mi = 0; mi < 2; mi++)
#pragma unroll
                for (int ni = 0; ni < 8; ni++)
                    mma_tf32(acc[mi][ni], a[mi], b[ni]);
        }
        __syncthreads();

        // rotate stages
        float* ta = a_cur; a_cur = a_nxt; a_nxt = a_spr; a_spr = ta;
        float* tb = b_cur; b_cur = b_nxt; b_nxt = b_spr; b_spr = tb;
    }

    // epilogue
#pragma unroll
    for (int mi = 0; mi < 2; mi++) {
        int row0 = rowBase + wm + mi * 16 + g;
        int row1 = row0 + 8;
#pragma unroll
        for (int ni = 0; ni < 8; ni++) {
            int col = colBase + wn + ni * 8 + t * 2;
            if (row0 < M)
                *(float2*)(C + (size_t)row0 * N + col) =
                    make_float2(acc[mi][ni][0], acc[mi][ni][1]);
            if (row1 < M)
                *(float2*)(C + (size_t)row1 * N + col) =
                    make_float2(acc[mi][ni][2], acc[mi][ni][3]);
        }
    }
}

// ---------------- aggregation layer 1: 512 features, 1 warp / node ----------------
__global__ __launch_bounds__(256)
void agg1_kernel(const float* __restrict__ b1) {
    int node = blockIdx.x * 8 + (threadIdx.x >> 5);
    if (node >= N_NODES) return;
    int lane = threadIdx.x & 31;
    const float4* h = (const float4*)g_h1;
    float dc = g_dis[node];

    float4 acc[4];
#pragma unroll
    for (int i = 0; i < 4; i++) {
        float4 v = h[(size_t)node * 128 + lane + i * 32];
        acc[i] = make_float4(v.x * dc, v.y * dc, v.z * dc, v.w * dc);
    }
    int beg = g_rowptr[node], end = g_rowptr[node + 1];
    for (int e = beg; e < end; e++) {
        int r = g_src[e];
        float w = g_wgt[e];
        const float4* hr = h + (size_t)r * 128;
#pragma unroll
        for (int i = 0; i < 4; i++) {
            float4 v = hr[lane + i * 32];
            acc[i].x += w * v.x; acc[i].y += w * v.y;
            acc[i].z += w * v.z; acc[i].w += w * v.w;
        }
    }
    float4* out = (float4*)g_a1;
    const float4* bb4 = (const float4*)b1;
#pragma unroll
    for (int i = 0; i < 4; i++) {
        float4 bb = bb4[lane + i * 32];
        float4 o;
        o.x = fmaxf(dc * acc[i].x + bb.x, 0.f);
        o.y = fmaxf(dc * acc[i].y + bb.y, 0.f);
        o.z = fmaxf(dc * acc[i].z + bb.z, 0.f);
        o.w = fmaxf(dc * acc[i].w + bb.w, 0.f);
        out[(size_t)node * 128 + lane + i * 32] = o;
    }
}

// ---------------- aggregation layer 2 fused with FC(128->14)+sigmoid ----------------
__global__ __launch_bounds__(256)
void agg2_fc_kernel(const float* __restrict__ b2, const float* __restrict__ Wfc,
                    const float* __restrict__ bfc, float* __restrict__ out) {
    __shared__ float sh[8][128];
    __shared__ float sWfc[D2 * DOUT];
    for (int i = threadIdx.x; i < D2 * DOUT; i += blockDim.x) sWfc[i] = Wfc[i];
    __syncthreads();

    int wid = threadIdx.x >> 5;
    int lane = threadIdx.x & 31;
    int node = blockIdx.x * 8 + wid;

    if (node < N_NODES) {
        const float4* h = (const float4*)g_h2;
        float dc = g_dis[node];
        float4 v = h[(size_t)node * 32 + lane];
        float4 acc = make_float4(v.x * dc, v.y * dc, v.z * dc, v.w * dc);
        int beg = g_rowptr[node], end = g_rowptr[node + 1];
        for (int e = beg; e < end; e++) {
            int r = g_src[e];
            float w = g_wgt[e];
            float4 u = h[(size_t)r * 32 + lane];
            acc.x += w * u.x; acc.y += w * u.y; acc.z += w * u.z; acc.w += w * u.w;
        }
        float4 bb = ((const float4*)b2)[lane];
        sh[wid][lane * 4 + 0] = fmaxf(dc * acc.x + bb.x, 0.f);
        sh[wid][lane * 4 + 1] = fmaxf(dc * acc.y + bb.y, 0.f);
        sh[wid][lane * 4 + 2] = fmaxf(dc * acc.z + bb.z, 0.f);
        sh[wid][lane * 4 + 3] = fmaxf(dc * acc.w + bb.w, 0.f);
    }
    __syncwarp();
    if (node < N_NODES && lane < DOUT) {
        float s = bfc[lane];
#pragma unroll 8
        for (int d = 0; d < D2; d++) s += sh[wid][d] * sWfc[d * DOUT + lane];
        out[(size_t)node * DOUT + lane] = 1.f / (1.f + expf(-s));
    }
}

// ---------------- launch ----------------
// Launch order puts tf32gemm (GEMM1) as the 6th launch so ncu (-s 5 -c 1)
// profiles it instead of the tiny preproc kernels.
extern "C" void kernel_launch(void* const* d_in, const int* in_sizes, int n_in,
                              void* d_out, int out_size) {
    const float* x   = (const float*)d_in[0];
    const void*  eix = d_in[1];
    const float* ew  = (const float*)d_in[2];
    const float* W1  = (const float*)d_in[3];
    const float* b1  = (const float*)d_in[4];
    const float* W2  = (const float*)d_in[5];
    const float* b2  = (const float*)d_in[6];
    const float* Wfc = (const float*)d_in[7];
    const float* bfc = (const float*)d_in[8];
    float* out = (float*)d_out;

    float *h1p, *a1p, *h2p;
    cudaGetSymbolAddress((void**)&h1p, g_h1);
    cudaGetSymbolAddress((void**)&a1p, g_a1);
    cudaGetSymbolAddress((void**)&h2p, g_h2);

    cudaFuncSetAttribute(tf32gemm, cudaFuncAttributeMaxDynamicSharedMemorySize,
                         GEMM_SMEM_BYTES);

    const int TB = 256;
    detect_idx_kernel<<<1, 32>>>(eix);                              // 1
    init_kernel<<<(N_NODES + TB - 1) / TB, TB>>>();                 // 2
    edge_deg_kernel<<<(N_EDGES + TB - 1) / TB, TB>>>(eix, ew);      // 3
    dis_kernel<<<(N_NODES + TB - 1) / TB, TB>>>();                  // 4
    scan_kernel<<<1, 1024>>>();                                     // 5

    dim3 g1(D1 / BN, (N_NODES + BM - 1) / BM);
    tf32gemm<<<g1, 256, GEMM_SMEM_BYTES>>>(x, W1, h1p, N_NODES, D0, D1);  // 6 <- ncu

    scatter_kernel<<<(N_EDGES + TB - 1) / TB, TB>>>(eix, ew);       // 7

    agg1_kernel<<<(N_NODES + 7) / 8, 256>>>(b1);                    // 8

    dim3 g2(D2 / BN, (N_NODES + BM - 1) / BM);
    tf32gemm<<<g2, 256, GEMM_SMEM_BYTES>>>(a1p, W2, h2p, N_NODES, D1, D2);  // 9

    agg2_fc_kernel<<<(N_NODES + 7) / 8, 256>>>(b2, Wfc, bfc, out);  // 10
}